// round 5
// baseline (speedup 1.0000x reference)
#include <cuda_runtime.h>

// Problem constants
#define BB     256        // batch rows
#define DD     256        // feature dim
#define NCOLS  131072     // 2*N feature rows
#define NHALF  65536      // N
#define TC     64         // columns per CTA
#define KC     8          // K-chunk
#define TEMP_INV 20.0f    // 1/0.05
#define SHIFT    20.0f    // max |logit| bound (|dot|<=1)
#define RR     0.2f

// Scratch: [0..255] = mean-half exp sums, [256..511] = hard-half exp sums
__device__ float g_sums[2 * BB];
__device__ float g_tgt[2 * BB];   // target logits (already scaled by 1/TEMP)

__global__ void init_kernel() {
    int t = threadIdx.x;
    if (t < 2 * BB) g_sums[t] = 0.0f;
}

// Fused GEMM + exp row-sum. Grid: NCOLS/TC blocks of 256 threads.
// Each block: all 256 batch rows x 64 feature columns, K=256.
__global__ __launch_bounds__(256) void main_kernel(const float* __restrict__ inp,
                                                   const float* __restrict__ feat) {
    __shared__ float As[KC][BB];        // 8 x 256 (k-major inputs)
    __shared__ float Bs[KC][TC];        // 8 x 64  (k-major feature tile)
    __shared__ float red[BB][8];        // per-row partial exp sums across col-groups

    const int t   = threadIdx.x;
    const int ry  = t & 31;             // row group  (rows ry*8 .. ry*8+7)
    const int cx  = t >> 5;             // col group  (cols cx*8 .. cx*8+7)
    const int col0 = blockIdx.x * TC;

    float acc[8][8];
#pragma unroll
    for (int i = 0; i < 8; i++)
#pragma unroll
        for (int j = 0; j < 8; j++) acc[i][j] = 0.0f;

    for (int k0 = 0; k0 < DD; k0 += KC) {
        // Load input chunk transposed: As[kk][row] = inp[row*DD + k0 + kk]
#pragma unroll
        for (int i = 0; i < 8; i++) {
            int e   = t + i * 256;      // 0..2047
            int row = e >> 3;
            int kk  = e & 7;
            As[kk][row] = inp[row * DD + k0 + kk];
        }
        // Load feature tile transposed: Bs[kk][c] = feat[(col0+c)*DD + k0 + kk]
#pragma unroll
        for (int i = 0; i < 2; i++) {
            int e  = t + i * 256;       // 0..511
            int c  = e >> 3;
            int kk = e & 7;
            Bs[kk][c] = feat[(size_t)(col0 + c) * DD + k0 + kk];
        }
        __syncthreads();

#pragma unroll
        for (int k = 0; k < KC; k++) {
            float a[8], b[8];
#pragma unroll
            for (int j = 0; j < 8; j++) a[j] = As[k][ry * 8 + j];
#pragma unroll
            for (int j = 0; j < 8; j++) b[j] = Bs[k][cx * 8 + j];
#pragma unroll
            for (int i = 0; i < 8; i++)
#pragma unroll
                for (int j = 0; j < 8; j++)
                    acc[i][j] = fmaf(a[i], b[j], acc[i][j]);
        }
        __syncthreads();
    }

    // Epilogue: exp(logit - SHIFT), logit = dot * TEMP_INV, dot in [-1,1]
#pragma unroll
    for (int i = 0; i < 8; i++) {
        float s = 0.0f;
#pragma unroll
        for (int j = 0; j < 8; j++)
            s += __expf(fmaf(acc[i][j], TEMP_INV, -SHIFT));
        red[ry * 8 + i][cx] = s;
    }
    __syncthreads();

    // Thread t reduces row t across the 8 col-groups, one atomic per row per CTA
    float v = 0.0f;
#pragma unroll
    for (int j = 0; j < 8; j++) v += red[t][j];
    const int half = (col0 >= NHALF) ? 1 : 0;
    atomicAdd(&g_sums[half * BB + t], v);
}

// One warp per (batch row, half): dot(inputs[b], features[target(+N)])
// Targets dtype detection (int32 vs int64), done safely inside the warp:
// if stored as int64 (values < 2^16), the int32 view has 0 at every odd
// index; if int32, odd indices are random targets. We ballot over the first
// 64 int32 words (256 bytes — within the minimum buffer size either way).
__global__ void tgt_kernel(const float* __restrict__ inp,
                           const float* __restrict__ feat,
                           const void* __restrict__ targets) {
    const int b = blockIdx.x >> 1;
    const int h = blockIdx.x & 1;
    const int lane = threadIdx.x;

    const int* p32 = (const int*)targets;
    unsigned odd_nonzero = __ballot_sync(0xffffffffu, p32[2 * lane + 1] != 0);
    const bool is64 = (odd_nonzero == 0u);

    long long tb;
    if (is64) tb = ((const long long*)targets)[b];
    else      tb = (long long)p32[b];

    const long long col = tb + (long long)h * NHALF;
    const float* fa = feat + col * DD;
    const float* ia = inp + (size_t)b * DD;

    float s = 0.0f;
    for (int k = lane; k < DD; k += 32)
        s = fmaf(ia[k], fa[k], s);
#pragma unroll
    for (int o = 16; o > 0; o >>= 1)
        s += __shfl_xor_sync(0xffffffffu, s, o);
    if (lane == 0) g_tgt[h * BB + b] = s * TEMP_INV;
}

// Fold to scalar loss. One block of 256 threads.
__global__ void final_kernel(float* __restrict__ out) {
    const int t = threadIdx.x;
    // half 0 = mean logits (cols [0,N)), half 1 = hard logits (cols [N,2N))
    float lse_m = logf(g_sums[t])       + SHIFT;
    float lse_h = logf(g_sums[BB + t])  + SHIFT;
    float dm = lse_m - g_tgt[t];         // -logp_target (mean)
    float dh = lse_h - g_tgt[BB + t];    // -logp_target (hard)

    // block reduction of dm, dh
    __shared__ float smm[8], smh[8];
#pragma unroll
    for (int o = 16; o > 0; o >>= 1) {
        dm += __shfl_xor_sync(0xffffffffu, dm, o);
        dh += __shfl_xor_sync(0xffffffffu, dh, o);
    }
    if ((t & 31) == 0) { smm[t >> 5] = dm; smh[t >> 5] = dh; }
    __syncthreads();
    if (t == 0) {
        float sm = 0.0f, sh = 0.0f;
#pragma unroll
        for (int i = 0; i < 8; i++) { sm += smm[i]; sh += smh[i]; }
        float ce_m = sm * (1.0f / BB);
        float ce_h = sh * (1.0f / BB);
        out[0] = 0.5f * (ce_h + fmaxf(ce_m - RR, 0.0f));
    }
}

extern "C" void kernel_launch(void* const* d_in, const int* in_sizes, int n_in,
                              void* d_out, int out_size) {
    const float* inp     = (const float*)d_in[0];   // (256, 256) f32
    const void*  targets = d_in[1];                 // (256,) int32 or int64 (auto-detected)
    const float* feat    = (const float*)d_in[2];   // (131072, 256) f32
    float* out = (float*)d_out;

    init_kernel<<<1, 512>>>();
    main_kernel<<<NCOLS / TC, 256>>>(inp, feat);
    tgt_kernel<<<2 * BB, 32>>>(inp, feat, targets);
    final_kernel<<<1, 256>>>(out);
}

// round 9
// speedup vs baseline: 6.3338x; 6.3338x over previous
#include <cuda_runtime.h>
#include <cuda_bf16.h>
#include <cstdint>

// ---------------- problem constants ----------------
#define BB      256
#define DD      256
#define NCOLS   131072
#define NHALF   65536
#define TN      128        // feature cols per tile
#define NTILES  (NCOLS / TN)   // 1024
#define KCH     64         // K per B chunk
#define TEMP_INV 20.0f
#define SHIFT    20.0f
#define RR       0.2f

// smem: red[256] floats @0 (1024B), A @1024 (256 rows x 512B = 131072B),
//       B double buffer @132096 (2 x 128 rows x 128B = 32768B)
#define SM_A      1024u
#define SM_B      (SM_A + 131072u)
#define SM_TOTAL  (SM_B + 32768u)   // 164864

__device__ float g_sums[2 * BB];
__device__ float g_tgt[2 * BB];
__device__ uint4 g_Abf4[BB * 32];   // inputs as bf16 row-major, 32 x 16B chunks/row

// ---------------- helpers ----------------
__device__ __forceinline__ uint32_t smem_u32(const void* p) {
    uint32_t a;
    asm("{ .reg .u64 t; cvta.to.shared.u64 t, %1; cvt.u32.u64 %0, t; }" : "=r"(a) : "l"(p));
    return a;
}
#define CVT_BF2(res, a, b) asm("cvt.rn.satfinite.bf16x2.f32 %0, %1, %2;" : "=r"(res) : "f"(b), "f"(a))

#define LDSM_X4(r, a) asm volatile( \
    "ldmatrix.sync.aligned.m8n8.x4.shared.b16 {%0,%1,%2,%3}, [%4];" \
    : "=r"((r)[0]), "=r"((r)[1]), "=r"((r)[2]), "=r"((r)[3]) : "r"(a))
#define LDSM_X2(r, a) asm volatile( \
    "ldmatrix.sync.aligned.m8n8.x2.shared.b16 {%0,%1}, [%2];" \
    : "=r"((r)[0]), "=r"((r)[1]) : "r"(a))
#define MMA16816(d, a, b) asm volatile( \
    "mma.sync.aligned.m16n8k16.row.col.f32.bf16.bf16.f32 " \
    "{%0,%1,%2,%3}, {%4,%5,%6,%7}, {%8,%9}, {%0,%1,%2,%3};" \
    : "+f"((d)[0]), "+f"((d)[1]), "+f"((d)[2]), "+f"((d)[3]) \
    : "r"((a)[0]), "r"((a)[1]), "r"((a)[2]), "r"((a)[3]), "r"((b)[0]), "r"((b)[1]))

// ---------------- prep: zero sums + convert inputs to bf16 ----------------
__global__ void prep_kernel(const float* __restrict__ inp) {
    const int t = threadIdx.x;
    g_sums[t] = 0.0f;
    g_sums[BB + t] = 0.0f;
    const float4* src = (const float4*)inp + t * 64;
#pragma unroll
    for (int j = 0; j < 32; j++) {
        float4 a = src[2 * j], b = src[2 * j + 1];
        uint4 pk;
        CVT_BF2(pk.x, a.x, a.y); CVT_BF2(pk.y, a.z, a.w);
        CVT_BF2(pk.z, b.x, b.y); CVT_BF2(pk.w, b.z, b.w);
        g_Abf4[t * 32 + j] = pk;
    }
}

// B chunk staging (each thread: 16 floats = one quarter of one feature row-chunk)
__device__ __forceinline__ void loadB(const float* __restrict__ feat, size_t col0,
                                      int kc, int t, float4 f4[4]) {
    const float4* s = (const float4*)(feat + (col0 + (size_t)(t >> 2)) * DD
                                      + kc * KCH + (t & 3) * 16);
    f4[0] = s[0]; f4[1] = s[1]; f4[2] = s[2]; f4[3] = s[3];
}
__device__ __forceinline__ void storeB(char* Bsm, int slot, int t, const float4 f4[4]) {
    const int n = t >> 2, seg = t & 3;
    uint4 p0, p1;
    CVT_BF2(p0.x, f4[0].x, f4[0].y); CVT_BF2(p0.y, f4[0].z, f4[0].w);
    CVT_BF2(p0.z, f4[1].x, f4[1].y); CVT_BF2(p0.w, f4[1].z, f4[1].w);
    CVT_BF2(p1.x, f4[2].x, f4[2].y); CVT_BF2(p1.y, f4[2].z, f4[2].w);
    CVT_BF2(p1.z, f4[3].x, f4[3].y); CVT_BF2(p1.w, f4[3].z, f4[3].w);
    char* base = Bsm + slot * 16384 + n * 128;
    *(uint4*)(base + (((seg * 2)     ^ (n & 7)) * 16)) = p0;
    *(uint4*)(base + (((seg * 2 + 1) ^ (n & 7)) * 16)) = p1;
}

// ---------------- persistent fused GEMM (HMMA) + exp row-sum ----------------
__global__ void __launch_bounds__(512, 1) main_kernel(const float* __restrict__ feat) {
    extern __shared__ __align__(1024) char smem[];
    float* red = (float*)smem;
    char* Asm = smem + SM_A;
    char* Bsm = smem + SM_B;
    const uint32_t Abase = smem_u32(Asm), Bbase = smem_u32(Bsm);

    const int t = threadIdx.x, lane = t & 31, wid = t >> 5;
    const int wm = wid & 3;           // 4 M-groups of 64 rows
    const int wn = wid >> 2;          // 4 N-groups of 32 cols

    // ---- cache A (256x256 bf16) in swizzled smem, once per CTA ----
#pragma unroll
    for (int i = 0; i < 16; i++) {
        int g = t + i * 512;          // 16B chunk id 0..8191
        int row = g >> 5, c = g & 31;
        *(uint4*)(Asm + row * 512 + ((c ^ (row & 7)) * 16)) = g_Abf4[g];
    }

    for (int tile = blockIdx.x; tile < NTILES; tile += gridDim.x) {
        const size_t col0 = (size_t)tile * TN;
        if (t < 256) red[t] = 0.0f;

        float d[4][4][4];
#pragma unroll
        for (int mt = 0; mt < 4; mt++)
#pragma unroll
            for (int nt = 0; nt < 4; nt++)
#pragma unroll
                for (int q = 0; q < 4; q++) d[mt][nt][q] = 0.0f;

        // chunk 0: load + convert + store slot 0
        {
            float4 f4[4];
            loadB(feat, col0, 0, t, f4);
            storeB(Bsm, 0, t, f4);
        }
        __syncthreads();

        for (int kc = 0; kc < 4; kc++) {
            float4 f4[4];
            if (kc < 3) loadB(feat, col0, kc + 1, t, f4);   // prefetch under MMA

            const uint32_t Bslot = Bbase + (kc & 1) * 16384u;
#pragma unroll
            for (int ks = 0; ks < 4; ks++) {
                const int gks = kc * 4 + ks;
                uint32_t a[4][4];
#pragma unroll
                for (int mt = 0; mt < 4; mt++) {
                    int r = wm * 64 + mt * 16 + (lane & 15);
                    uint32_t addr = Abase + r * 512
                                  + (((2 * gks + (lane >> 4)) ^ (r & 7)) * 16);
                    LDSM_X4(a[mt], addr);
                }
                uint32_t b[4][2];
#pragma unroll
                for (int nt = 0; nt < 4; nt++) {
                    int n = wn * 32 + nt * 8 + (lane & 7);
                    uint32_t addr = Bslot + n * 128
                                  + (((2 * ks + ((lane >> 3) & 1)) ^ (n & 7)) * 16);
                    LDSM_X2(b[nt], addr);
                }
#pragma unroll
                for (int mt = 0; mt < 4; mt++)
#pragma unroll
                    for (int nt = 0; nt < 4; nt++)
                        MMA16816(d[mt][nt], a[mt], b[nt]);
            }

            if (kc < 3) {
                storeB(Bsm, (kc + 1) & 1, t, f4);
                __syncthreads();
            }
        }

        // ---- epilogue: exp + row reduction ----
        // D m16n8 layout: lane -> row groupID=lane>>2 (+8 for d2/d3), cols lane&3.
#pragma unroll
        for (int mt = 0; mt < 4; mt++) {
            float slo = 0.0f, shi = 0.0f;
#pragma unroll
            for (int nt = 0; nt < 4; nt++) {
                slo += __expf(fmaf(d[mt][nt][0], TEMP_INV, -SHIFT))
                     + __expf(fmaf(d[mt][nt][1], TEMP_INV, -SHIFT));
                shi += __expf(fmaf(d[mt][nt][2], TEMP_INV, -SHIFT))
                     + __expf(fmaf(d[mt][nt][3], TEMP_INV, -SHIFT));
            }
#pragma unroll
            for (int o = 1; o <= 2; o <<= 1) {
                slo += __shfl_xor_sync(0xffffffffu, slo, o);
                shi += __shfl_xor_sync(0xffffffffu, shi, o);
            }
            if ((lane & 3) == 0) {
                int r = wm * 64 + mt * 16 + (lane >> 2);
                atomicAdd(&red[r], slo);
                atomicAdd(&red[r + 8], shi);
            }
        }
        __syncthreads();
        if (t < 256) {
            const int half = (tile >= (NTILES / 2)) ? BB : 0;
            atomicAdd(&g_sums[half + t], red[t]);
        }
        __syncthreads();
    }
}

// ---------------- target logits (fp32, exact) ----------------
__global__ void tgt_kernel(const float* __restrict__ inp,
                           const float* __restrict__ feat,
                           const void* __restrict__ targets) {
    const int b = blockIdx.x >> 1;
    const int h = blockIdx.x & 1;
    const int lane = threadIdx.x;

    const int* p32 = (const int*)targets;
    unsigned odd_nz = __ballot_sync(0xffffffffu, p32[2 * lane + 1] != 0);
    const bool is64 = (odd_nz == 0u);
    long long tb = is64 ? ((const long long*)targets)[b] : (long long)p32[b];

    const float* fa = feat + (tb + (long long)h * NHALF) * DD;
    const float* ia = inp + (size_t)b * DD;
    float s = 0.0f;
    for (int k = lane; k < DD; k += 32) s = fmaf(ia[k], fa[k], s);
#pragma unroll
    for (int o = 16; o > 0; o >>= 1) s += __shfl_xor_sync(0xffffffffu, s, o);
    if (lane == 0) g_tgt[h * BB + b] = s * TEMP_INV;
}

// ---------------- fold to scalar ----------------
__global__ void final_kernel(float* __restrict__ out) {
    const int t = threadIdx.x;
    float dm = (logf(g_sums[t]) + SHIFT) - g_tgt[t];
    float dh = (logf(g_sums[BB + t]) + SHIFT) - g_tgt[BB + t];
    __shared__ float smm[8], smh[8];
#pragma unroll
    for (int o = 16; o > 0; o >>= 1) {
        dm += __shfl_xor_sync(0xffffffffu, dm, o);
        dh += __shfl_xor_sync(0xffffffffu, dh, o);
    }
    if ((t & 31) == 0) { smm[t >> 5] = dm; smh[t >> 5] = dh; }
    __syncthreads();
    if (t == 0) {
        float sm = 0.0f, sh = 0.0f;
#pragma unroll
        for (int i = 0; i < 8; i++) { sm += smm[i]; sh += smh[i]; }
        out[0] = 0.5f * (sh * (1.0f / BB) + fmaxf(sm * (1.0f / BB) - RR, 0.0f));
    }
}

extern "C" void kernel_launch(void* const* d_in, const int* in_sizes, int n_in,
                              void* d_out, int out_size) {
    const float* inp     = (const float*)d_in[0];
    const void*  targets = d_in[1];
    const float* feat    = (const float*)d_in[2];
    float* out = (float*)d_out;

    cudaFuncSetAttribute(main_kernel, cudaFuncAttributeMaxDynamicSharedMemorySize, SM_TOTAL);

    prep_kernel<<<1, 256>>>(inp);
    main_kernel<<<148, 512, SM_TOTAL>>>(feat);
    tgt_kernel<<<2 * BB, 32>>>(inp, feat, targets);
    final_kernel<<<1, 256>>>(out);
}

// round 11
// speedup vs baseline: 7.5550x; 1.1928x over previous
#include <cuda_runtime.h>
#include <cuda_bf16.h>
#include <cstdint>

// ---------------- problem constants ----------------
#define BB      256
#define DD      256
#define NCOLS   131072
#define NHALF   65536
#define TN      128
#define NTILES  (NCOLS / TN)    // 1024
#define NGRID   148
#define TEMP_INV 20.0f
#define SHIFT    20.0f
#define RR       0.2f

// smem: acc[512] @0 (2048B), A @2048 (256x512B=131072B), B @133120 (3x16384B)
#define SM_A      2048u
#define SM_B      (SM_A + 131072u)
#define SM_TOTAL  (SM_B + 3u * 16384u)   // 182272

__device__ float g_sums[2 * BB];
__device__ float g_tgt[2 * BB];

// ---------------- helpers ----------------
__device__ __forceinline__ uint32_t smem_u32(const void* p) {
    uint32_t a;
    asm("{ .reg .u64 t; cvta.to.shared.u64 t, %1; cvt.u32.u64 %0, t; }" : "=r"(a) : "l"(p));
    return a;
}
#define CVT_BF2(res, a, b) asm("cvt.rn.satfinite.bf16x2.f32 %0, %1, %2;" : "=r"(res) : "f"(b), "f"(a))

#define LDSM_X4(r, a) asm volatile( \
    "ldmatrix.sync.aligned.m8n8.x4.shared.b16 {%0,%1,%2,%3}, [%4];" \
    : "=r"((r)[0]), "=r"((r)[1]), "=r"((r)[2]), "=r"((r)[3]) : "r"(a))
#define LDSM_X2(r, a) asm volatile( \
    "ldmatrix.sync.aligned.m8n8.x2.shared.b16 {%0,%1}, [%2];" \
    : "=r"((r)[0]), "=r"((r)[1]) : "r"(a))
#define MMA16816(d, a, b) asm volatile( \
    "mma.sync.aligned.m16n8k16.row.col.f32.bf16.bf16.f32 " \
    "{%0,%1,%2,%3}, {%4,%5,%6,%7}, {%8,%9}, {%0,%1,%2,%3};" \
    : "+f"((d)[0]), "+f"((d)[1]), "+f"((d)[2]), "+f"((d)[3]) \
    : "r"((a)[0]), "r"((a)[1]), "r"((a)[2]), "r"((a)[3]), "r"((b)[0]), "r"((b)[1]))

// B chunk staging: thread t covers feature row col0 + (t>>2), k-quarter (t&3)
__device__ __forceinline__ void loadB(const float* __restrict__ feat, size_t col0,
                                      int kc, int t, float4 f4[4]) {
    const float4* s = (const float4*)(feat + (col0 + (size_t)(t >> 2)) * DD
                                      + kc * 64 + (t & 3) * 16);
    f4[0] = s[0]; f4[1] = s[1]; f4[2] = s[2]; f4[3] = s[3];
}
__device__ __forceinline__ void storeB(char* Bsm, int slot, int t, const float4 f4[4]) {
    const int n = t >> 2, seg = t & 3;
    uint4 p0, p1;
    CVT_BF2(p0.x, f4[0].x, f4[0].y); CVT_BF2(p0.y, f4[0].z, f4[0].w);
    CVT_BF2(p0.z, f4[1].x, f4[1].y); CVT_BF2(p0.w, f4[1].z, f4[1].w);
    CVT_BF2(p1.x, f4[2].x, f4[2].y); CVT_BF2(p1.y, f4[2].z, f4[2].w);
    CVT_BF2(p1.z, f4[3].x, f4[3].y); CVT_BF2(p1.w, f4[3].z, f4[3].w);
    char* base = Bsm + slot * 16384 + n * 128;
    *(uint4*)(base + (((seg * 2)     ^ (n & 7)) * 16)) = p0;
    *(uint4*)(base + (((seg * 2 + 1) ^ (n & 7)) * 16)) = p1;
}

// ---------------- persistent fused GEMM (HMMA) + exp row-sum ----------------
__global__ void __launch_bounds__(512, 1) main_kernel(const float* __restrict__ inp,
                                                      const float* __restrict__ feat) {
    extern __shared__ __align__(1024) char smem[];
    float* acc = (float*)smem;                 // [2][256] persistent row sums
    char* Asm = smem + SM_A;
    char* Bsm = smem + SM_B;
    const uint32_t Abase = smem_u32(Asm), Bbase = smem_u32(Bsm);

    const int t = threadIdx.x, lane = t & 31, wid = t >> 5;
    const int wm = wid & 3, wn = wid >> 2;
    const int bid = blockIdx.x;

    if (t < 512) acc[t] = 0.0f;

    // ---- prologue: convert+cache A (256x256 f32 -> bf16, swizzled) ----
#pragma unroll
    for (int i = 0; i < 16; i++) {
        int g = t + i * 512;                   // 16B bf16 chunk id 0..8191
        int row = g >> 5, c = g & 31;
        const float4* s = (const float4*)(inp + row * DD + c * 8);
        float4 a = s[0], b = s[1];
        uint4 pk;
        CVT_BF2(pk.x, a.x, a.y); CVT_BF2(pk.y, a.z, a.w);
        CVT_BF2(pk.z, b.x, b.y); CVT_BF2(pk.w, b.z, b.w);
        *(uint4*)(Asm + row * 512 + ((c ^ (row & 7)) * 16)) = pk;
    }

    const int nt_cta = (NTILES - bid + NGRID - 1) / NGRID;   // tiles for this CTA
    const int total = nt_cta * 4;                            // chunks

    float d[4][4][4];
#pragma unroll
    for (int mt = 0; mt < 4; mt++)
#pragma unroll
        for (int nt = 0; nt < 4; nt++)
#pragma unroll
            for (int q = 0; q < 4; q++) d[mt][nt][q] = 0.0f;

    float4 f4[4];
    loadB(feat, (size_t)bid * TN, 0, t, f4);   // chunk 0 -> regs
    __syncthreads();                            // A published

    for (int s = 0; s <= total; s++) {
        if (s < total) storeB(Bsm, s % 3, t, f4);
        if (s + 1 < total) {
            int c = s + 1;
            size_t col0 = (size_t)(bid + (c >> 2) * NGRID) * TN;
            loadB(feat, col0, c & 3, t, f4);
        }
        __syncthreads();

        if (s >= 1) {
            const int c = s - 1;                // MMA this chunk
            const uint32_t Bslot = Bbase + (uint32_t)(c % 3) * 16384u;
            const int kc = c & 3;
#pragma unroll
            for (int ks = 0; ks < 4; ks++) {
                const int gks = kc * 4 + ks;
                uint32_t a[4][4];
#pragma unroll
                for (int mt = 0; mt < 4; mt++) {
                    int r = wm * 64 + mt * 16 + (lane & 15);
                    uint32_t addr = Abase + r * 512
                                  + (((2 * gks + (lane >> 4)) ^ (r & 7)) * 16);
                    LDSM_X4(a[mt], addr);
                }
                uint32_t b[4][2];
#pragma unroll
                for (int nt = 0; nt < 4; nt++) {
                    int n = wn * 32 + nt * 8 + (lane & 7);
                    uint32_t addr = Bslot + n * 128
                                  + (((2 * ks + ((lane >> 3) & 1)) ^ (n & 7)) * 16);
                    LDSM_X2(b[nt], addr);
                }
#pragma unroll
                for (int mt = 0; mt < 4; mt++)
#pragma unroll
                    for (int nt = 0; nt < 4; nt++)
                        MMA16816(d[mt][nt], a[mt], b[nt]);
            }

            if (kc == 3) {                      // tile finished: fused epilogue
                const int tile = bid + (c >> 2) * NGRID;
                float* ah = acc + ((tile >= NTILES / 2) ? 256 : 0);
#pragma unroll
                for (int mt = 0; mt < 4; mt++) {
                    float slo = 0.0f, shi = 0.0f;
#pragma unroll
                    for (int nt = 0; nt < 4; nt++) {
                        slo += __expf(fmaf(d[mt][nt][0], TEMP_INV, -SHIFT))
                             + __expf(fmaf(d[mt][nt][1], TEMP_INV, -SHIFT));
                        shi += __expf(fmaf(d[mt][nt][2], TEMP_INV, -SHIFT))
                             + __expf(fmaf(d[mt][nt][3], TEMP_INV, -SHIFT));
#pragma unroll
                        for (int q = 0; q < 4; q++) d[mt][nt][q] = 0.0f;
                    }
#pragma unroll
                    for (int o = 1; o <= 2; o <<= 1) {
                        slo += __shfl_xor_sync(0xffffffffu, slo, o);
                        shi += __shfl_xor_sync(0xffffffffu, shi, o);
                    }
                    if ((lane & 3) == 0) {
                        int r = wm * 64 + mt * 16 + (lane >> 2);
                        atomicAdd(&ah[r], slo);
                        atomicAdd(&ah[r + 8], shi);
                    }
                }
            }
        }
    }

    __syncthreads();
    atomicAdd(&g_sums[t], acc[t]);              // single flush, layout matches
}

// ---------------- targets + g_sums init (runs BEFORE main) ----------------
__global__ void tgt_kernel(const float* __restrict__ inp,
                           const float* __restrict__ feat,
                           const void* __restrict__ targets) {
    const int b = blockIdx.x >> 1;
    const int h = blockIdx.x & 1;
    const int lane = threadIdx.x;

    if (blockIdx.x == 0) {
#pragma unroll
        for (int i = 0; i < 16; i++) g_sums[lane + i * 32] = 0.0f;
    }

    const int* p32 = (const int*)targets;
    unsigned odd_nz = __ballot_sync(0xffffffffu, p32[2 * lane + 1] != 0);
    const bool is64 = (odd_nz == 0u);
    long long tb = is64 ? ((const long long*)targets)[b] : (long long)p32[b];

    const float* fa = feat + (tb + (long long)h * NHALF) * DD;
    const float* ia = inp + (size_t)b * DD;
    float s = 0.0f;
    for (int k = lane; k < DD; k += 32) s = fmaf(ia[k], fa[k], s);
#pragma unroll
    for (int o = 16; o > 0; o >>= 1) s += __shfl_xor_sync(0xffffffffu, s, o);
    if (lane == 0) g_tgt[h * BB + b] = s * TEMP_INV;
}

// ---------------- fold to scalar ----------------
__global__ void final_kernel(float* __restrict__ out) {
    const int t = threadIdx.x;
    float dm = (logf(g_sums[t]) + SHIFT) - g_tgt[t];
    float dh = (logf(g_sums[BB + t]) + SHIFT) - g_tgt[BB + t];
    __shared__ float smm[8], smh[8];
#pragma unroll
    for (int o = 16; o > 0; o >>= 1) {
        dm += __shfl_xor_sync(0xffffffffu, dm, o);
        dh += __shfl_xor_sync(0xffffffffu, dh, o);
    }
    if ((t & 31) == 0) { smm[t >> 5] = dm; smh[t >> 5] = dh; }
    __syncthreads();
    if (t == 0) {
        float sm = 0.0f, sh = 0.0f;
#pragma unroll
        for (int i = 0; i < 8; i++) { sm += smm[i]; sh += smh[i]; }
        out[0] = 0.5f * (sh * (1.0f / BB) + fmaxf(sm * (1.0f / BB) - RR, 0.0f));
    }
}

extern "C" void kernel_launch(void* const* d_in, const int* in_sizes, int n_in,
                              void* d_out, int out_size) {
    const float* inp     = (const float*)d_in[0];
    const void*  targets = d_in[1];
    const float* feat    = (const float*)d_in[2];
    float* out = (float*)d_out;

    cudaFuncSetAttribute(main_kernel, cudaFuncAttributeMaxDynamicSharedMemorySize, SM_TOTAL);

    tgt_kernel<<<2 * BB, 32>>>(inp, feat, targets);
    main_kernel<<<NGRID, 512, SM_TOTAL>>>(inp, feat);
    final_kernel<<<1, 256>>>(out);
}